// round 1
// baseline (speedup 1.0000x reference)
#include <cuda_runtime.h>
#include <math.h>

#define HID 256
#define NF  64

// Precomputed Gram matrix G = feature_emb @ feature_emb.T  (64x64)
__device__ float d_G[NF * NF];

__global__ void compute_G_kernel(const float* __restrict__ fe) {
    int i = blockIdx.x, j = threadIdx.x;
    const float4* a = (const float4*)(fe + i * HID);
    const float4* b = (const float4*)(fe + j * HID);
    float s = 0.f;
#pragma unroll 8
    for (int k = 0; k < HID / 4; k++) {
        float4 x = a[k], y = b[k];
        s = fmaf(x.x, y.x, fmaf(x.y, y.y, fmaf(x.z, y.z, fmaf(x.w, y.w, s))));
    }
    d_G[i * NF + j] = s;
}

// ---- packed f32x2 helpers (FFMA2 path; ptxas never emits this from C++) ----
__device__ __forceinline__ unsigned long long pk2(float lo, float hi) {
    unsigned long long r;
    asm("mov.b64 %0,{%1,%2};" : "=l"(r) : "f"(lo), "f"(hi));
    return r;
}
__device__ __forceinline__ void up2(unsigned long long v, float& lo, float& hi) {
    asm("mov.b64 {%0,%1},%2;" : "=f"(lo), "=f"(hi) : "l"(v));
}
__device__ __forceinline__ void fma2(unsigned long long& d, unsigned long long a,
                                     unsigned long long b) {
    asm("fma.rn.f32x2 %0,%1,%2,%0;" : "+l"(d) : "l"(a), "l"(b));
}
__device__ __forceinline__ float gelu_exact(float x) {
    return 0.5f * x * (1.f + erff(x * 0.7071067811865476f));
}

// acc = A(4 rows from smem, K cols, row stride ASTRIDE) @ W (K x 256)
// acc[r][0..1] -> cols [c0..c0+3], acc[r][2..3] -> cols [c0+128..c0+131]
template <int K, int ASTRIDE>
__device__ __forceinline__ void gemm_n256(const float* __restrict__ W, const float* As,
                                          int lane, unsigned long long acc[4][4]) {
    const int c0 = lane * 4;
#pragma unroll 1
    for (int k = 0; k < K; k += 4) {
        float4 a4[4];
#pragma unroll
        for (int r = 0; r < 4; r++) a4[r] = *(const float4*)(As + r * ASTRIDE + k);
#pragma unroll
        for (int kk = 0; kk < 4; kk++) {
            float4 w0 = *(const float4*)(W + (k + kk) * 256 + c0);
            float4 w1 = *(const float4*)(W + (k + kk) * 256 + c0 + 128);
            unsigned long long w00 = pk2(w0.x, w0.y), w01 = pk2(w0.z, w0.w);
            unsigned long long w10 = pk2(w1.x, w1.y), w11 = pk2(w1.z, w1.w);
#pragma unroll
            for (int r = 0; r < 4; r++) {
                float av = ((const float*)&a4[r])[kk];
                unsigned long long aa = pk2(av, av);
                fma2(acc[r][0], aa, w00);
                fma2(acc[r][1], aa, w01);
                fma2(acc[r][2], aa, w10);
                fma2(acc[r][3], aa, w11);
            }
        }
    }
}

extern "C" __global__ void __launch_bounds__(256, 2)
arn_fused(const float* __restrict__ known_mask, const int* __restrict__ obs_idx,
          const int* __restrict__ obs_mask_idx, const int* __restrict__ attr_idx,
          const float* __restrict__ obs_embs,
          const float* __restrict__ rm_W1, const float* __restrict__ rm_b1,
          const float* __restrict__ rm_W2, const float* __restrict__ rm_b2,
          const float* __restrict__ rr_W, const float* __restrict__ rr_b,
          const float* __restrict__ rc_W, const float* __restrict__ rc_b,
          float* __restrict__ out, int E) {
    // per-warp private slices: warp w owns rows [4w, 4w+4)
    __shared__ float sm_f[32 * NF];   // holds softmax(m) in phases A/B, then x in C/D
    __shared__ float sm_h[32 * HID];  // holds h1 (B->C), then y (D->E)

    const int w = threadIdx.x >> 5;
    const int lane = threadIdx.x & 31;
    const int row0 = w * 4;
    const long base = (long)blockIdx.x * 32 + row0;
    const int c0 = lane * 4;

    int oiv[4], atv[4];
    bool valid[4];
    int omiv[4];
#pragma unroll
    for (int r = 0; r < 4; r++) {
        long e = base + r;
        valid[r] = (e < E);
        long ec = valid[r] ? e : (long)(E - 1);
        oiv[r] = obs_idx[ec];
        omiv[r] = obs_mask_idx[ec];
        atv[r] = attr_idx[ec];
    }

    // ---- Phase A: m = softmax(known_mask[omi] * (1 - e_attr)) over F=64 ----
#pragma unroll
    for (int r = 0; r < 4; r++) {
        const float* km = known_mask + (long)omiv[r] * NF;
        float v0 = km[lane];
        float v1 = km[lane + 32];
        if (lane == atv[r]) v0 = 0.f;
        if (lane + 32 == atv[r]) v1 = 0.f;
        float mx = fmaxf(v0, v1);
#pragma unroll
        for (int o = 16; o > 0; o >>= 1) mx = fmaxf(mx, __shfl_xor_sync(0xffffffffu, mx, o));
        float e0 = expf(v0 - mx), e1 = expf(v1 - mx);
        float s = e0 + e1;
#pragma unroll
        for (int o = 16; o > 0; o >>= 1) s += __shfl_xor_sync(0xffffffffu, s, o);
        float inv = 1.f / s;
        sm_f[(row0 + r) * NF + lane] = e0 * inv;
        sm_f[(row0 + r) * NF + lane + 32] = e1 * inv;
    }
    __syncwarp();

    // ---- Phase B: h1 = gelu(m @ rm_W1 + rm_b1)   [4 x 256], K=64 ----
    {
        unsigned long long acc[4][4] = {};
        gemm_n256<NF, NF>(rm_W1, sm_f + row0 * NF, lane, acc);
        float4 bA = *(const float4*)(rm_b1 + c0);
        float4 bB = *(const float4*)(rm_b1 + c0 + 128);
#pragma unroll
        for (int r = 0; r < 4; r++) {
            float v[8];
            up2(acc[r][0], v[0], v[1]);
            up2(acc[r][1], v[2], v[3]);
            up2(acc[r][2], v[4], v[5]);
            up2(acc[r][3], v[6], v[7]);
            float4 oA, oB;
            oA.x = gelu_exact(v[0] + bA.x);
            oA.y = gelu_exact(v[1] + bA.y);
            oA.z = gelu_exact(v[2] + bA.z);
            oA.w = gelu_exact(v[3] + bA.w);
            oB.x = gelu_exact(v[4] + bB.x);
            oB.y = gelu_exact(v[5] + bB.y);
            oB.z = gelu_exact(v[6] + bB.z);
            oB.w = gelu_exact(v[7] + bB.w);
            *(float4*)(sm_h + (row0 + r) * HID + c0) = oA;
            *(float4*)(sm_h + (row0 + r) * HID + c0 + 128) = oB;
        }
    }
    __syncwarp();

    // ---- Phase C: mJ = gelu(h1 @ rm_W2 + rm_b2); x = G[attr] * mJ  [4 x 64], K=256 ----
    {
        unsigned long long accC[4] = {0ull, 0ull, 0ull, 0ull};
        const int cc = lane * 2;
#pragma unroll 1
        for (int k = 0; k < HID; k += 4) {
            float4 a4[4];
#pragma unroll
            for (int r = 0; r < 4; r++) a4[r] = *(const float4*)(sm_h + (row0 + r) * HID + k);
#pragma unroll
            for (int kk = 0; kk < 4; kk++) {
                float2 wv = *(const float2*)(rm_W2 + (k + kk) * NF + cc);
                unsigned long long wp = pk2(wv.x, wv.y);
#pragma unroll
                for (int r = 0; r < 4; r++) {
                    float av = ((const float*)&a4[r])[kk];
                    fma2(accC[r], pk2(av, av), wp);
                }
            }
        }
        float2 b2v = *(const float2*)(rm_b2 + cc);
#pragma unroll
        for (int r = 0; r < 4; r++) {
            float x0, x1;
            up2(accC[r], x0, x1);
            x0 = gelu_exact(x0 + b2v.x);
            x1 = gelu_exact(x1 + b2v.y);
            float2 g = *(const float2*)(d_G + atv[r] * NF + cc);
            sm_f[(row0 + r) * NF + cc] = x0 * g.x;
            sm_f[(row0 + r) * NF + cc + 1] = x1 * g.y;
        }
    }
    __syncwarp();

    // ---- Phase D: a = gelu(x @ rr_W + rr_b); y = obs_h * a  [4 x 256], K=64 ----
    {
        unsigned long long acc[4][4] = {};
        gemm_n256<NF, NF>(rr_W, sm_f + row0 * NF, lane, acc);
        float4 bA = *(const float4*)(rr_b + c0);
        float4 bB = *(const float4*)(rr_b + c0 + 128);
#pragma unroll
        for (int r = 0; r < 4; r++) {
            float v[8];
            up2(acc[r][0], v[0], v[1]);
            up2(acc[r][1], v[2], v[3]);
            up2(acc[r][2], v[4], v[5]);
            up2(acc[r][3], v[6], v[7]);
            float4 hA = *(const float4*)(obs_embs + (long)oiv[r] * HID + c0);
            float4 hB = *(const float4*)(obs_embs + (long)oiv[r] * HID + c0 + 128);
            float4 oA, oB;
            oA.x = gelu_exact(v[0] + bA.x) * hA.x;
            oA.y = gelu_exact(v[1] + bA.y) * hA.y;
            oA.z = gelu_exact(v[2] + bA.z) * hA.z;
            oA.w = gelu_exact(v[3] + bA.w) * hA.w;
            oB.x = gelu_exact(v[4] + bB.x) * hB.x;
            oB.y = gelu_exact(v[5] + bB.y) * hB.y;
            oB.z = gelu_exact(v[6] + bB.z) * hB.z;
            oB.w = gelu_exact(v[7] + bB.w) * hB.w;
            *(float4*)(sm_h + (row0 + r) * HID + c0) = oA;
            *(float4*)(sm_h + (row0 + r) * HID + c0 + 128) = oB;
        }
    }
    __syncwarp();

    // ---- Phase E: out = gelu(y @ rc_W + rc_b)  [4 x 256], K=256 ----
    {
        unsigned long long acc[4][4] = {};
        gemm_n256<HID, HID>(rc_W, sm_h + row0 * HID, lane, acc);
        float4 bA = *(const float4*)(rc_b + c0);
        float4 bB = *(const float4*)(rc_b + c0 + 128);
#pragma unroll
        for (int r = 0; r < 4; r++) {
            if (!valid[r]) continue;
            float v[8];
            up2(acc[r][0], v[0], v[1]);
            up2(acc[r][1], v[2], v[3]);
            up2(acc[r][2], v[4], v[5]);
            up2(acc[r][3], v[6], v[7]);
            float4 oA, oB;
            oA.x = gelu_exact(v[0] + bA.x);
            oA.y = gelu_exact(v[1] + bA.y);
            oA.z = gelu_exact(v[2] + bA.z);
            oA.w = gelu_exact(v[3] + bA.w);
            oB.x = gelu_exact(v[4] + bB.x);
            oB.y = gelu_exact(v[5] + bB.y);
            oB.z = gelu_exact(v[6] + bB.z);
            oB.w = gelu_exact(v[7] + bB.w);
            *(float4*)(out + (base + r) * HID + c0) = oA;
            *(float4*)(out + (base + r) * HID + c0 + 128) = oB;
        }
    }
}

extern "C" void kernel_launch(void* const* d_in, const int* in_sizes, int n_in,
                              void* d_out, int out_size) {
    const float* known_mask = (const float*)d_in[0];
    const int* obs_idx = (const int*)d_in[1];
    const int* obs_mask_idx = (const int*)d_in[2];
    const int* attr_idx = (const int*)d_in[3];
    const float* obs_embs = (const float*)d_in[4];
    const float* feature_emb = (const float*)d_in[5];
    const float* rm_W1 = (const float*)d_in[6];
    const float* rm_b1 = (const float*)d_in[7];
    const float* rm_W2 = (const float*)d_in[8];
    const float* rm_b2 = (const float*)d_in[9];
    const float* rr_W = (const float*)d_in[10];
    const float* rr_b = (const float*)d_in[11];
    const float* rc_W = (const float*)d_in[12];
    const float* rc_b = (const float*)d_in[13];
    int E = in_sizes[1];

    compute_G_kernel<<<NF, NF>>>(feature_emb);
    int grid = (E + 31) / 32;
    arn_fused<<<grid, 256>>>(known_mask, obs_idx, obs_mask_idx, attr_idx, obs_embs,
                             rm_W1, rm_b1, rm_W2, rm_b2, rr_W, rr_b, rc_W, rc_b,
                             (float*)d_out, E);
}